// round 1
// baseline (speedup 1.0000x reference)
#include <cuda_runtime.h>

// ============================================================================
// ScaledDotProductAttention: B=4, S=2048, D=1024, fp32.
//   Q = X Wq^T ; K = X Wk^T ; V = X Wv^T            (NT gemms, M=8192)
//   S = (Q K^T) / 32  per batch                      (NT gemm,  M=N=2048)
//   P = softmax_rows(S)
//   AO = P V  per batch                              (NN gemm)
//   OUT = AO Wo^T                                    (NT gemm)
// All exact fp32 (FFMA), so rel_err ~ 1e-6. Baseline for tensor-core rounds.
// ============================================================================

#define BMT 128
#define BNT 128
#define BKT 8
#define TM 8
#define TN 8
#define PADT 4

// Scratch (static device memory — allocation-guard safe).
__device__ float g_Q [8192 * 1024];
__device__ float g_K [8192 * 1024];
__device__ float g_V [8192 * 1024];
__device__ float g_S [16777216];      // 4 * 2048 * 2048
__device__ float g_AO[8192 * 1024];

// ----------------------------------------------------------------------------
// C[m,n] = alpha * sum_k A[m,k] * B[n,k]   (A: [M,K] rm, B: [N,K] rm)
// grid.z batches with element strides sA/sB/sC. Dims multiples of 128/8.
// ----------------------------------------------------------------------------
__global__ __launch_bounds__(256, 2)
void gemm_nt(const float* __restrict__ Ag, const float* __restrict__ Bg,
             float* __restrict__ Cg, int M, int N, int K, float alpha,
             long sA, long sB, long sC)
{
    const float* A = Ag + (long)blockIdx.z * sA;
    const float* B = Bg + (long)blockIdx.z * sB;
    float*       C = Cg + (long)blockIdx.z * sC;

    __shared__ float As[2][BKT][BMT + PADT];
    __shared__ float Bs[2][BKT][BNT + PADT];

    const int tid = threadIdx.x;
    const int bm  = blockIdx.y * BMT;
    const int bn  = blockIdx.x * BNT;

    // loader mapping: 256 threads, 128x8 tile, float4 per thread
    const int lr = tid >> 1;          // 0..127 tile row
    const int lc = (tid & 1) * 4;     // 0 or 4 k-offset

    // compute mapping
    const int tm = (tid >> 4) * TM;
    const int tn = (tid & 15) * TN;

    float acc[TM][TN];
    #pragma unroll
    for (int i = 0; i < TM; i++)
        #pragma unroll
        for (int j = 0; j < TN; j++) acc[i][j] = 0.0f;

    // prologue: tile k0 = 0 into buffer 0
    {
        float4 a4 = *(const float4*)(A + (long)(bm + lr) * K + lc);
        float4 b4 = *(const float4*)(B + (long)(bn + lr) * K + lc);
        As[0][lc + 0][lr] = a4.x; As[0][lc + 1][lr] = a4.y;
        As[0][lc + 2][lr] = a4.z; As[0][lc + 3][lr] = a4.w;
        Bs[0][lc + 0][lr] = b4.x; Bs[0][lc + 1][lr] = b4.y;
        Bs[0][lc + 2][lr] = b4.z; Bs[0][lc + 3][lr] = b4.w;
    }
    __syncthreads();

    int buf = 0;
    for (int k0 = 0; k0 < K; k0 += BKT) {
        float4 a4, b4;
        const bool more = (k0 + BKT) < K;
        if (more) {
            a4 = *(const float4*)(A + (long)(bm + lr) * K + k0 + BKT + lc);
            b4 = *(const float4*)(B + (long)(bn + lr) * K + k0 + BKT + lc);
        }

        #pragma unroll
        for (int kk = 0; kk < BKT; kk++) {
            float ar[TM], br[TN];
            #pragma unroll
            for (int i = 0; i < TM; i++) ar[i] = As[buf][kk][tm + i];
            #pragma unroll
            for (int j = 0; j < TN; j++) br[j] = Bs[buf][kk][tn + j];
            #pragma unroll
            for (int i = 0; i < TM; i++)
                #pragma unroll
                for (int j = 0; j < TN; j++)
                    acc[i][j] = fmaf(ar[i], br[j], acc[i][j]);
        }

        if (more) {
            As[buf ^ 1][lc + 0][lr] = a4.x; As[buf ^ 1][lc + 1][lr] = a4.y;
            As[buf ^ 1][lc + 2][lr] = a4.z; As[buf ^ 1][lc + 3][lr] = a4.w;
            Bs[buf ^ 1][lc + 0][lr] = b4.x; Bs[buf ^ 1][lc + 1][lr] = b4.y;
            Bs[buf ^ 1][lc + 2][lr] = b4.z; Bs[buf ^ 1][lc + 3][lr] = b4.w;
        }
        __syncthreads();
        buf ^= 1;
    }

    #pragma unroll
    for (int i = 0; i < TM; i++) {
        #pragma unroll
        for (int j = 0; j < TN; j += 4) {
            float4 v = make_float4(acc[i][j] * alpha, acc[i][j + 1] * alpha,
                                   acc[i][j + 2] * alpha, acc[i][j + 3] * alpha);
            *(float4*)(C + (long)(bm + tm + i) * N + bn + tn + j) = v;
        }
    }
}

// ----------------------------------------------------------------------------
// C[m,n] = sum_k A[m,k] * B[k,n]   (A: [M,K] rm, B: [K,N] rm)
// ----------------------------------------------------------------------------
__global__ __launch_bounds__(256, 2)
void gemm_nn(const float* __restrict__ Ag, const float* __restrict__ Bg,
             float* __restrict__ Cg, int M, int N, int K,
             long sA, long sB, long sC)
{
    const float* A = Ag + (long)blockIdx.z * sA;
    const float* B = Bg + (long)blockIdx.z * sB;
    float*       C = Cg + (long)blockIdx.z * sC;

    __shared__ float As[2][BKT][BMT + PADT];
    __shared__ float Bs[2][BKT][BNT];

    const int tid = threadIdx.x;
    const int bm  = blockIdx.y * BMT;
    const int bn  = blockIdx.x * BNT;

    const int lr  = tid >> 1;            // A loader: 0..127 row
    const int lc  = (tid & 1) * 4;       // A loader: k offset
    const int brw = tid >> 5;            // B loader: 0..7 k-row
    const int bcl = (tid & 31) * 4;      // B loader: 0..124 n-col

    const int tm = (tid >> 4) * TM;
    const int tn = (tid & 15) * TN;

    float acc[TM][TN];
    #pragma unroll
    for (int i = 0; i < TM; i++)
        #pragma unroll
        for (int j = 0; j < TN; j++) acc[i][j] = 0.0f;

    {
        float4 a4 = *(const float4*)(A + (long)(bm + lr) * K + lc);
        float4 b4 = *(const float4*)(B + (long)brw * N + bn + bcl);
        As[0][lc + 0][lr] = a4.x; As[0][lc + 1][lr] = a4.y;
        As[0][lc + 2][lr] = a4.z; As[0][lc + 3][lr] = a4.w;
        *(float4*)&Bs[0][brw][bcl] = b4;
    }
    __syncthreads();

    int buf = 0;
    for (int k0 = 0; k0 < K; k0 += BKT) {
        float4 a4, b4;
        const bool more = (k0 + BKT) < K;
        if (more) {
            a4 = *(const float4*)(A + (long)(bm + lr) * K + k0 + BKT + lc);
            b4 = *(const float4*)(B + (long)(k0 + BKT + brw) * N + bn + bcl);
        }

        #pragma unroll
        for (int kk = 0; kk < BKT; kk++) {
            float ar[TM], br[TN];
            #pragma unroll
            for (int i = 0; i < TM; i++) ar[i] = As[buf][kk][tm + i];
            #pragma unroll
            for (int j = 0; j < TN; j++) br[j] = Bs[buf][kk][tn + j];
            #pragma unroll
            for (int i = 0; i < TM; i++)
                #pragma unroll
                for (int j = 0; j < TN; j++)
                    acc[i][j] = fmaf(ar[i], br[j], acc[i][j]);
        }

        if (more) {
            As[buf ^ 1][lc + 0][lr] = a4.x; As[buf ^ 1][lc + 1][lr] = a4.y;
            As[buf ^ 1][lc + 2][lr] = a4.z; As[buf ^ 1][lc + 3][lr] = a4.w;
            *(float4*)&Bs[buf ^ 1][brw][bcl] = b4;
        }
        __syncthreads();
        buf ^= 1;
    }

    #pragma unroll
    for (int i = 0; i < TM; i++) {
        #pragma unroll
        for (int j = 0; j < TN; j += 4) {
            float4 v = make_float4(acc[i][j], acc[i][j + 1],
                                   acc[i][j + 2], acc[i][j + 3]);
            *(float4*)(C + (long)(bm + tm + i) * N + bn + tn + j) = v;
        }
    }
}

// ----------------------------------------------------------------------------
// In-place row softmax, rows of length 2048, one 256-thread block per row.
// ----------------------------------------------------------------------------
__global__ void softmax2048(float* __restrict__ Sg)
{
    float4* row = (float4*)(Sg + (long)blockIdx.x * 2048);
    const int tid = threadIdx.x;

    float4 a = row[tid];
    float4 b = row[tid + 256];
    float v[8] = { a.x, a.y, a.z, a.w, b.x, b.y, b.z, b.w };

    float m = -1e30f;
    #pragma unroll
    for (int i = 0; i < 8; i++) m = fmaxf(m, v[i]);
    #pragma unroll
    for (int o = 16; o; o >>= 1) m = fmaxf(m, __shfl_xor_sync(0xffffffffu, m, o));

    __shared__ float red[8];
    if ((tid & 31) == 0) red[tid >> 5] = m;
    __syncthreads();
    m = red[0];
    #pragma unroll
    for (int i = 1; i < 8; i++) m = fmaxf(m, red[i]);

    float s = 0.0f;
    #pragma unroll
    for (int i = 0; i < 8; i++) { v[i] = expf(v[i] - m); s += v[i]; }
    #pragma unroll
    for (int o = 16; o; o >>= 1) s += __shfl_xor_sync(0xffffffffu, s, o);

    __syncthreads();                       // red reuse
    if ((tid & 31) == 0) red[tid >> 5] = s;
    __syncthreads();
    s = 0.0f;
    #pragma unroll
    for (int i = 0; i < 8; i++) s += red[i];

    const float inv = 1.0f / s;
    #pragma unroll
    for (int i = 0; i < 8; i++) v[i] *= inv;

    row[tid]       = make_float4(v[0], v[1], v[2], v[3]);
    row[tid + 256] = make_float4(v[4], v[5], v[6], v[7]);
}

// ----------------------------------------------------------------------------
extern "C" void kernel_launch(void* const* d_in, const int* in_sizes, int n_in,
                              void* d_out, int out_size)
{
    (void)in_sizes; (void)n_in; (void)out_size;
    const float* x  = (const float*)d_in[0];
    const float* wq = (const float*)d_in[1];
    const float* wk = (const float*)d_in[2];
    const float* wv = (const float*)d_in[3];
    const float* wo = (const float*)d_in[4];
    float* out = (float*)d_out;

    float *Q, *K, *V, *S, *AO;
    cudaGetSymbolAddress((void**)&Q,  g_Q);
    cudaGetSymbolAddress((void**)&K,  g_K);
    cudaGetSymbolAddress((void**)&V,  g_V);
    cudaGetSymbolAddress((void**)&S,  g_S);
    cudaGetSymbolAddress((void**)&AO, g_AO);

    const int Bb = 4, Sq = 2048, D = 1024, MB = 8192;
    dim3 thr(256);

    // QKV projections: [8192,1024] = X[8192,1024] @ W^T
    gemm_nt<<<dim3(D / BNT, MB / BMT, 1), thr>>>(x, wq, Q, MB, D, D, 1.0f, 0, 0, 0);
    gemm_nt<<<dim3(D / BNT, MB / BMT, 1), thr>>>(x, wk, K, MB, D, D, 1.0f, 0, 0, 0);
    gemm_nt<<<dim3(D / BNT, MB / BMT, 1), thr>>>(x, wv, V, MB, D, D, 1.0f, 0, 0, 0);

    // scores = Q K^T / sqrt(1024), per batch
    gemm_nt<<<dim3(Sq / BNT, Sq / BMT, Bb), thr>>>(Q, K, S, Sq, Sq, D, 0.03125f,
                                                   (long)Sq * D, (long)Sq * D,
                                                   (long)Sq * Sq);
    // softmax over keys
    softmax2048<<<Bb * Sq, 256>>>(S);

    // AO = P V, per batch
    gemm_nn<<<dim3(D / BNT, Sq / BMT, Bb), thr>>>(S, V, AO, Sq, D, Sq,
                                                  (long)Sq * Sq, (long)Sq * D,
                                                  (long)Sq * D);
    // OUT = AO Wo^T
    gemm_nt<<<dim3(D / BNT, MB / BMT, 1), thr>>>(AO, wo, out, MB, D, D, 1.0f, 0, 0, 0);
}

// round 3
// speedup vs baseline: 2.4021x; 2.4021x over previous
#include <cuda_runtime.h>
#include <cuda_bf16.h>
#include <cstdint>

// ============================================================================
// ScaledDotProductAttention via mma.sync (HMMA) bf16 GEMMs with hi/lo fp32
// emulation. (tcgen05 is unavailable: harness targets plain sm_100.)
// Every GEMM is NT: C[m,n] = sum_k A[m,k]*B[n,k], operands bf16 K-major,
// K-dim concatenated as A=[hi|hi|lo], B=[hi|lo|hi]  (3x K, fp32 accum).
// ============================================================================

// ---------------- PTX helpers ----------------
__device__ __forceinline__ uint32_t smem_u32(const void* p) {
    uint32_t a;
    asm("{ .reg .u64 t; cvta.to.shared.u64 t, %1; cvt.u32.u64 %0, t; }"
        : "=r"(a) : "l"(p));
    return a;
}
__device__ __forceinline__ void cp16(uint32_t dst, const void* src) {
    asm volatile("cp.async.cg.shared.global [%0], [%1], 16;" :: "r"(dst), "l"(src));
}
__device__ __forceinline__ void cp_commit() {
    asm volatile("cp.async.commit_group;" ::: "memory");
}
template <int N>
__device__ __forceinline__ void cp_wait() {
    asm volatile("cp.async.wait_group %0;" :: "n"(N) : "memory");
}
__device__ __forceinline__ void ldsm_x4(uint32_t& r0, uint32_t& r1, uint32_t& r2,
                                        uint32_t& r3, uint32_t a) {
    asm volatile("ldmatrix.sync.aligned.m8n8.x4.shared.b16 {%0,%1,%2,%3}, [%4];"
                 : "=r"(r0), "=r"(r1), "=r"(r2), "=r"(r3) : "r"(a));
}
__device__ __forceinline__ void mma_bf16(float* c, const uint32_t* a,
                                         uint32_t b0, uint32_t b1) {
    asm volatile(
        "mma.sync.aligned.m16n8k16.row.col.f32.bf16.bf16.f32 "
        "{%0,%1,%2,%3}, {%4,%5,%6,%7}, {%8,%9}, {%0,%1,%2,%3};"
        : "+f"(c[0]), "+f"(c[1]), "+f"(c[2]), "+f"(c[3])
        : "r"(a[0]), "r"(a[1]), "r"(a[2]), "r"(a[3]), "r"(b0), "r"(b1));
}
__device__ __forceinline__ uint32_t swz(uint32_t o) { return o ^ ((o >> 3) & 0x70); }

// ---------------- scratch (__device__ globals) ----------------
__device__ __nv_bfloat16 g_X3 [8192L * 3072];
__device__ __nv_bfloat16 g_W3 [4][1024L * 3072];
__device__ __nv_bfloat16 g_Q3 [8192L * 3072];
__device__ __nv_bfloat16 g_K3 [8192L * 3072];
__device__ float         g_V  [8192L * 1024];
__device__ __nv_bfloat16 g_Vt3[4][1024L * 6144];
__device__ float         g_S  [4L * 2048 * 2048];
__device__ __nv_bfloat16 g_P3 [4][2048L * 6144];
__device__ __nv_bfloat16 g_AO3[8192L * 3072];

// ---------------- HMMA GEMM ----------------
// BM=BN=128, BK=64 bf16 (128B rows, swizzled). NS-stage cp.async pipeline.
// 8 warps: 4 along M (32 rows each) x 2 along N (64 cols each).
#define NS 3
#define A_STG 16384
#define B_STG 16384
#define SMEM_DYN (1024 + NS * (A_STG + B_STG))

// mode: 0 = fp32 out (ld=Ntot, *alpha); 1 = bf16 split A-pattern [hi|hi|lo];
//       2 = bf16 split B-pattern [hi|lo|hi] (ld = 3*Ntot)
__global__ __launch_bounds__(256, 2)
void gemm_tc(const __nv_bfloat16* __restrict__ Ag, const __nv_bfloat16* __restrict__ Bg,
             void* __restrict__ Cout, int Ntot, int Kcat, float alpha, int mode,
             long long sA, long long sB, long long sC)
{
    extern __shared__ char dsm[];
    const uint32_t sb  = (smem_u32(dsm) + 1023u) & ~1023u;
    const uint32_t sA0 = sb;
    const uint32_t sB0 = sb + NS * A_STG;

    const int tid  = threadIdx.x;
    const int wid  = tid >> 5;
    const int lane = tid & 31;
    const int wm   = wid & 3;     // warp row block (32 rows)
    const int wn   = wid >> 2;    // warp col block (64 cols)

    const __nv_bfloat16* A = Ag + blockIdx.z * sA + (long long)blockIdx.y * 128 * Kcat;
    const __nv_bfloat16* B = Bg + blockIdx.z * sB + (long long)blockIdx.x * 128 * Kcat;

    const int NC = Kcat >> 6;     // 64-element K chunks

    auto load_chunk = [&](int c, int stg) {
        const int k0 = c << 6;
        #pragma unroll
        for (int i = 0; i < 4; i++) {           // A: 128 rows x 8 x 16B
            int slot = tid + i * 256;
            int row = slot >> 3, seg = slot & 7;
            cp16(sA0 + stg * A_STG + swz(row * 128 + seg * 16),
                 A + (long long)row * Kcat + k0 + seg * 8);
        }
        #pragma unroll
        for (int i = 0; i < 4; i++) {           // B: 128 rows x 8 x 16B
            int slot = tid + i * 256;
            int row = slot >> 3, seg = slot & 7;
            cp16(sB0 + stg * B_STG + swz(row * 128 + seg * 16),
                 B + (long long)row * Kcat + k0 + seg * 8);
        }
        cp_commit();
    };

    float acc[2][8][4];
    #pragma unroll
    for (int i = 0; i < 2; i++)
        #pragma unroll
        for (int j = 0; j < 8; j++)
            #pragma unroll
            for (int k = 0; k < 4; k++) acc[i][j][k] = 0.0f;

    // prologue
    #pragma unroll
    for (int s = 0; s < NS - 1; s++) load_chunk(s, s);

    for (int c = 0; c < NC; c++) {
        if (c + NS - 1 < NC) cp_wait<NS - 2>(); else cp_wait<0>();
        __syncthreads();
        if (c + NS - 1 < NC) load_chunk(c + NS - 1, (c + NS - 1) % NS);

        const int stg = c % NS;
        const uint32_t aB = sA0 + stg * A_STG;
        const uint32_t bB = sB0 + stg * B_STG;

        #pragma unroll
        for (int ks = 0; ks < 4; ks++) {
            const int ch = ks * 2 + (lane >> 4);
            uint32_t a[2][4];
            #pragma unroll
            for (int mf = 0; mf < 2; mf++) {
                int row = wm * 32 + mf * 16 + (lane & 15);
                ldsm_x4(a[mf][0], a[mf][1], a[mf][2], a[mf][3],
                        aB + swz(row * 128 + ch * 16));
            }
            uint32_t b[4][4];
            #pragma unroll
            for (int bq = 0; bq < 4; bq++) {
                int row = wn * 64 + bq * 16 + (lane & 15);
                ldsm_x4(b[bq][0], b[bq][1], b[bq][2], b[bq][3],
                        bB + swz(row * 128 + ch * 16));
            }
            #pragma unroll
            for (int mf = 0; mf < 2; mf++)
                #pragma unroll
                for (int nf = 0; nf < 8; nf++) {
                    const int bq = nf >> 1, h = nf & 1;
                    mma_bf16(acc[mf][nf], a[mf], b[bq][h], b[bq][h + 2]);
                }
        }
    }

    // ---- epilogue (c-fragment layout: rows lane>>2 / +8, cols (lane&3)*2) ----
    const int rg = lane >> 2, tg = lane & 3;
    const long long rowBase = (long long)blockIdx.y * 128 + wm * 32;
    const long long colBase = (long long)blockIdx.x * 128 + wn * 64;

    #pragma unroll
    for (int mf = 0; mf < 2; mf++) {
        #pragma unroll
        for (int nf = 0; nf < 8; nf++) {
            const long long r0 = rowBase + mf * 16 + rg;
            const long long cc = colBase + nf * 8 + tg * 2;
            const float* v = acc[mf][nf];
            if (mode == 0) {
                float* Cf = (float*)Cout + blockIdx.z * sC;
                *(float2*)(Cf + r0 * Ntot + cc)       = make_float2(v[0] * alpha, v[1] * alpha);
                *(float2*)(Cf + (r0 + 8) * Ntot + cc) = make_float2(v[2] * alpha, v[3] * alpha);
            } else {
                __nv_bfloat16* Cb = (__nv_bfloat16*)Cout + blockIdx.z * sC;
                #pragma unroll
                for (int half = 0; half < 2; half++) {
                    const long long rr = r0 + half * 8;
                    float v0 = v[half * 2], v1 = v[half * 2 + 1];
                    __nv_bfloat16 h0 = __float2bfloat16(v0);
                    __nv_bfloat16 h1 = __float2bfloat16(v1);
                    __nv_bfloat16 l0 = __float2bfloat16(v0 - __bfloat162float(h0));
                    __nv_bfloat16 l1 = __float2bfloat16(v1 - __bfloat162float(h1));
                    __nv_bfloat162 hh = {h0, h1}, ll = {l0, l1};
                    __nv_bfloat16* o = Cb + rr * (3LL * Ntot) + cc;
                    *(__nv_bfloat162*)(o)            = hh;
                    *(__nv_bfloat162*)(o + Ntot)     = (mode == 1) ? hh : ll;
                    *(__nv_bfloat162*)(o + 2 * Ntot) = (mode == 1) ? ll : hh;
                }
            }
        }
    }
}

// ---------------- splits / transpose / softmax ----------------
__global__ void split_mat(const float* __restrict__ in, __nv_bfloat16* __restrict__ out,
                          long long n, int C, int mode)
{
    long long e = ((long long)blockIdx.x * blockDim.x + threadIdx.x) * 4;
    if (e >= n) return;
    float4 v = *(const float4*)(in + e);
    long long r = e / C;
    int c = (int)(e - r * C);
    __nv_bfloat16* o = out + r * (3LL * C) + c;
    float vv[4] = {v.x, v.y, v.z, v.w};
    __nv_bfloat16 h[4], l[4];
    #pragma unroll
    for (int i = 0; i < 4; i++) {
        h[i] = __float2bfloat16(vv[i]);
        l[i] = __float2bfloat16(vv[i] - __bfloat162float(h[i]));
    }
    #pragma unroll
    for (int i = 0; i < 4; i += 2) {
        __nv_bfloat162 hh = {h[i], h[i + 1]}, ll = {l[i], l[i + 1]};
        *(__nv_bfloat162*)(o + i)         = hh;
        *(__nv_bfloat162*)(o + C + i)     = (mode == 1) ? hh : ll;
        *(__nv_bfloat162*)(o + 2 * C + i) = (mode == 1) ? ll : hh;
    }
}

// V fp32 [4][2048][1024] -> Vt3 bf16 [4][1024][6144] (B-pattern [hi|lo|hi])
__global__ void vtrans_split(const float* __restrict__ V, __nv_bfloat16* __restrict__ out)
{
    __shared__ float t[32][33];
    const int b = blockIdx.z, s0 = blockIdx.y * 32, d0 = blockIdx.x * 32;
    const int tx = threadIdx.x, ty = threadIdx.y;
    const float* Vb = V + (long long)b * 2048 * 1024;
    #pragma unroll
    for (int i = 0; i < 4; i++) {
        int sy = ty + i * 8;
        t[sy][tx] = Vb[(long long)(s0 + sy) * 1024 + d0 + tx];
    }
    __syncthreads();
    __nv_bfloat16* ob = out + (long long)b * 1024 * 6144;
    #pragma unroll
    for (int i = 0; i < 4; i++) {
        int dy = ty + i * 8;
        float v = t[tx][dy];
        __nv_bfloat16 h = __float2bfloat16(v);
        __nv_bfloat16 l = __float2bfloat16(v - __bfloat162float(h));
        __nv_bfloat16* o = ob + (long long)(d0 + dy) * 6144 + s0 + tx;
        o[0]    = h;
        o[2048] = l;
        o[4096] = h;
    }
}

// softmax over 2048-wide rows of S, fused split to P3 (A-pattern [hi|hi|lo])
__global__ void softmax_split(const float* __restrict__ Sg, __nv_bfloat16* __restrict__ Pg)
{
    const float4* row = (const float4*)(Sg + (long long)blockIdx.x * 2048);
    const int tid = threadIdx.x;
    float4 a = row[tid];
    float4 b = row[tid + 256];
    float v[8] = {a.x, a.y, a.z, a.w, b.x, b.y, b.z, b.w};

    float m = -1e30f;
    #pragma unroll
    for (int i = 0; i < 8; i++) m = fmaxf(m, v[i]);
    #pragma unroll
    for (int o = 16; o; o >>= 1) m = fmaxf(m, __shfl_xor_sync(0xffffffffu, m, o));
    __shared__ float red[8];
    if ((tid & 31) == 0) red[tid >> 5] = m;
    __syncthreads();
    m = red[0];
    #pragma unroll
    for (int i = 1; i < 8; i++) m = fmaxf(m, red[i]);

    float s = 0.0f;
    #pragma unroll
    for (int i = 0; i < 8; i++) { v[i] = expf(v[i] - m); s += v[i]; }
    #pragma unroll
    for (int o = 16; o; o >>= 1) s += __shfl_xor_sync(0xffffffffu, s, o);
    __syncthreads();
    if ((tid & 31) == 0) red[tid >> 5] = s;
    __syncthreads();
    s = 0.0f;
    #pragma unroll
    for (int i = 0; i < 8; i++) s += red[i];
    const float inv = 1.0f / s;

    __nv_bfloat16* P = Pg + (long long)blockIdx.x * 6144;
    #pragma unroll
    for (int half = 0; half < 2; half++) {
        int c = tid * 4 + half * 1024;
        #pragma unroll
        for (int i = 0; i < 4; i += 2) {
            float p0 = v[half * 4 + i] * inv;
            float p1 = v[half * 4 + i + 1] * inv;
            __nv_bfloat16 h0 = __float2bfloat16(p0), h1 = __float2bfloat16(p1);
            __nv_bfloat16 l0 = __float2bfloat16(p0 - __bfloat162float(h0));
            __nv_bfloat16 l1 = __float2bfloat16(p1 - __bfloat162float(h1));
            __nv_bfloat162 hh = {h0, h1}, ll = {l0, l1};
            *(__nv_bfloat162*)(P + c + i)        = hh;
            *(__nv_bfloat162*)(P + 2048 + c + i) = hh;
            *(__nv_bfloat162*)(P + 4096 + c + i) = ll;
        }
    }
}

// ---------------- launch ----------------
extern "C" void kernel_launch(void* const* d_in, const int* in_sizes, int n_in,
                              void* d_out, int out_size)
{
    (void)in_sizes; (void)n_in; (void)out_size;
    const float* x  = (const float*)d_in[0];
    const float* w[4] = {(const float*)d_in[1], (const float*)d_in[2],
                         (const float*)d_in[3], (const float*)d_in[4]};
    float* out = (float*)d_out;

    __nv_bfloat16 *X3, *W3, *Q3, *K3, *Vt3, *P3, *AO3;
    float *V, *S;
    cudaGetSymbolAddress((void**)&X3,  g_X3);
    cudaGetSymbolAddress((void**)&W3,  g_W3);
    cudaGetSymbolAddress((void**)&Q3,  g_Q3);
    cudaGetSymbolAddress((void**)&K3,  g_K3);
    cudaGetSymbolAddress((void**)&V,   g_V);
    cudaGetSymbolAddress((void**)&Vt3, g_Vt3);
    cudaGetSymbolAddress((void**)&S,   g_S);
    cudaGetSymbolAddress((void**)&P3,  g_P3);
    cudaGetSymbolAddress((void**)&AO3, g_AO3);

    cudaFuncSetAttribute(gemm_tc, cudaFuncAttributeMaxDynamicSharedMemorySize, SMEM_DYN);

    // 1) input splits
    split_mat<<<8192, 256>>>(x, X3, 8192LL * 1024, 1024, 1);            // X: A-pattern
    for (int i = 0; i < 4; i++)
        split_mat<<<1024, 256>>>(w[i], W3 + (long long)i * 1024 * 3072,
                                 1024LL * 1024, 1024, 2);               // W: B-pattern

    // 2) projections: M=8192, N=1024, Kcat=3072
    dim3 gp(8, 64, 1);
    gemm_tc<<<gp, 256, SMEM_DYN>>>(X3, W3 + 0LL * 1024 * 3072, Q3,
                                   1024, 3072, 1.0f, 1, 0, 0, 0);       // Q: A-split
    gemm_tc<<<gp, 256, SMEM_DYN>>>(X3, W3 + 1LL * 1024 * 3072, K3,
                                   1024, 3072, 1.0f, 2, 0, 0, 0);       // K: B-split
    gemm_tc<<<gp, 256, SMEM_DYN>>>(X3, W3 + 2LL * 1024 * 3072, V,
                                   1024, 3072, 1.0f, 0, 0, 0, 0);       // V: fp32

    // 3) V transpose+split -> Vt3 [4][1024][6144]
    vtrans_split<<<dim3(32, 64, 4), dim3(32, 8)>>>(V, Vt3);

    // 4) scores = Q K^T / 32, per batch: M=N=2048, Kcat=3072
    gemm_tc<<<dim3(16, 16, 4), 256, SMEM_DYN>>>(Q3, K3, S, 2048, 3072,
                                                0.03125f, 0,
                                                2048LL * 3072, 2048LL * 3072,
                                                2048LL * 2048);

    // 5) softmax + split -> P3
    softmax_split<<<8192, 256>>>(S, P3);

    // 6) AO = P V, per batch: M=2048, N=1024, Kcat=6144 -> A-split
    gemm_tc<<<dim3(8, 16, 4), 256, SMEM_DYN>>>(P3, Vt3, AO3, 1024, 6144,
                                               1.0f, 1,
                                               2048LL * 6144, 1024LL * 6144,
                                               2048LL * 3072);

    // 7) OUT = AO Wo^T: fp32
    gemm_tc<<<gp, 256, SMEM_DYN>>>(AO3, W3 + 3LL * 1024 * 3072, out,
                                   1024, 3072, 1.0f, 0, 0, 0, 0);
}